// round 11
// baseline (speedup 1.0000x reference)
#include <cuda_runtime.h>
#include <cuda_bf16.h>
#include <cstdint>
#include <cstddef>

#define N_ROWS 500000
#define D_IN   128
#define R_DIM  256
#define D_OUT  64
#define U_DIM  10000
#define EPS    1e-8f
#define BM     64          // rows per block
#define NTHR   256         // 8 warps

// ---------------- precomputed weights (bf16, [n][k] layout) -----------------
__device__ __nv_bfloat16 g_w0mh[R_DIM * D_IN];
__device__ __nv_bfloat16 g_w0ml[R_DIM * D_IN];
__device__ __nv_bfloat16 g_w0vh[R_DIM * D_IN];
__device__ __nv_bfloat16 g_w1mh[D_OUT * R_DIM];
__device__ __nv_bfloat16 g_w1ml[D_OUT * R_DIM];
__device__ __nv_bfloat16 g_w1a1[D_OUT * R_DIM];
__device__ __nv_bfloat16 g_w1vh[D_OUT * R_DIM];
__device__ float g_sum_inv[U_DIM * D_OUT];
__device__ float g_sum_minv[U_DIM * D_OUT];

// ---------------- smem layout (bytes) ---------------------------------------
#define P0B 272
#define P1B 80
#define S_XH     0                     // 64*272 = 17408
#define S_X2H    17408
#define S_W0     34816                 // single stage x 3 mats x 32*272
#define W0_MAT   8704
#define S_W1     60928                 // 4 mats x 64*80 = 20480
#define W1_MAT   5120
#define S_L1MH   81408                 // 64*80 each
#define S_L1VH   86528
#define S_L12H   91648
#define S_UID    96768                 // 64*4
#define SMEM_SZ  97024
#define S_SINV   0                     // staging overlays XH (post-GEMM)
#define S_SMINV  17408                 // overlays X2H

// ---------------- helpers ----------------------------------------------------
static __device__ __forceinline__ uint32_t smem_u32(const void* p) {
    uint32_t a;
    asm("{ .reg .u64 t; cvta.to.shared.u64 t, %1; cvt.u32.u64 %0, t; }"
        : "=r"(a) : "l"(p));
    return a;
}
#define LDSM4(R, addr) \
    asm volatile("ldmatrix.sync.aligned.m8n8.x4.shared.b16 {%0,%1,%2,%3}, [%4];" \
        : "=r"((R)[0]), "=r"((R)[1]), "=r"((R)[2]), "=r"((R)[3]) : "r"(addr))
#define CP16(s, g) \
    asm volatile("cp.async.cg.shared.global [%0], [%1], 16;" :: "r"(s), "l"(g))
#define CP_COMMIT() asm volatile("cp.async.commit_group;" ::: "memory")
#define CP_WAIT(N)  asm volatile("cp.async.wait_group %0;" :: "n"(N) : "memory")

static __device__ __forceinline__ void mma16816(float* c, const uint32_t* a,
                                                const uint32_t* b) {
    asm volatile("mma.sync.aligned.m16n8k16.row.col.f32.bf16.bf16.f32 "
                 "{%0,%1,%2,%3},{%4,%5,%6,%7},{%8,%9},{%0,%1,%2,%3};"
                 : "+f"(c[0]), "+f"(c[1]), "+f"(c[2]), "+f"(c[3])
                 : "r"(a[0]), "r"(a[1]), "r"(a[2]), "r"(a[3]),
                   "r"(b[0]), "r"(b[1]));
}
static __device__ __forceinline__ void split2(float x, __nv_bfloat16& h,
                                              __nv_bfloat16& l) {
    h = __float2bfloat16(x);
    l = __float2bfloat16(x - __bfloat162float(h));
}
static __device__ __forceinline__ uint32_t pk(__nv_bfloat16 a, __nv_bfloat16 b) {
    return (uint32_t)__bfloat16_as_ushort(a) | ((uint32_t)__bfloat16_as_ushort(b) << 16);
}

// ---------------- prep -------------------------------------------------------
__global__ __launch_bounds__(256) void prep_kernel(const float* __restrict__ Wmu0,
                                                   const float* __restrict__ Wlv0,
                                                   const float* __restrict__ Wmu1,
                                                   const float* __restrict__ Wlv1) {
    int id = blockIdx.x * 256 + threadIdx.x;
    if (id < R_DIM * D_IN) {
        int n = id >> 7, k = id & 127;
        float wm = Wmu0[(size_t)k * R_DIM + n];
        float wv = expf(Wlv0[(size_t)k * R_DIM + n]);
        __nv_bfloat16 h, l;
        split2(wm, h, l);
        g_w0mh[id] = h;
        g_w0ml[id] = l;
        g_w0vh[id] = __float2bfloat16(wv);
    }
    if (id < D_OUT * R_DIM) {
        int n = id >> 8, k = id & 255;
        float wm = Wmu1[(size_t)k * D_OUT + n];
        float e  = expf(Wlv1[(size_t)k * D_OUT + n]);
        __nv_bfloat16 h, l;
        split2(wm, h, l);
        g_w1mh[id] = h;
        g_w1ml[id] = l;
        g_w1a1[id] = __float2bfloat16(wm * wm + e);
        g_w1vh[id] = __float2bfloat16(e);
    }
    if (id < U_DIM * D_OUT) { g_sum_inv[id] = 0.f; g_sum_minv[id] = 0.f; }
}

// ============================================================================
// Fused kernel: 64 rows/block, 256 threads (8 warps, grid 4m x 2n), 2 CTAs/SM.
// 8 weight chunks of 32; W0 single-buffered (cross-CTA overlap hides latency).
// Term scheme: L0 M = xh*(w0mh+w0ml), L0 V = x2h*w0vh,
//              L1 M = mh*(w1mh+w1ml), L1 V = vh*a1h + m2h*w1vh.
// ============================================================================
__global__ __launch_bounds__(NTHR, 2) void fused_kernel(const float* __restrict__ X,
                                                        const int* __restrict__ X_idx) {
    extern __shared__ char sm[];
    const uint32_t sb = smem_u32(sm);
    const int t = threadIdx.x, lane = t & 31, wid = t >> 5;
    const int wm_ = wid >> 1, wn = wid & 1;           // 4 x 2
    const int rowBase = blockIdx.x * BM;
    const int lr = lane & 7, sel = lane >> 3;

    // ---- prefetch W0[0] (32 rows x 16 units x 3 mats) -------------------------
    #pragma unroll
    for (int it = 0; it < 2; it++) {
        int idx = t + it * NTHR;
        int r = idx >> 4, kk = idx & 15;
        uint32_t so = sb + S_W0 + r * P0B + kk * 16;
        size_t go = (size_t)r * D_IN + kk * 8;
        CP16(so,              (const char*)&g_w0mh[go]);
        CP16(so + W0_MAT,     (const char*)&g_w0ml[go]);
        CP16(so + 2 * W0_MAT, (const char*)&g_w0vh[go]);
    }
    CP_COMMIT();

    if (t < BM) {
        int r = rowBase + t;
        *(int*)(sm + S_UID + t * 4) = (r < N_ROWS) ? X_idx[r] : -1;
    }

    // ---- phase 0: X tile 64 x 128 -> xh / x2h ----------------------------------
    #pragma unroll
    for (int it = 0; it < 8; it++) {
        int idx = t + it * NTHR;
        int row = idx >> 5;
        int k4  = (idx & 31) * 4;
        float4 v = make_float4(0.f, 0.f, 0.f, 0.f);
        if (rowBase + row < N_ROWS)
            v = *(const float4*)&X[(size_t)(rowBase + row) * D_IN + k4];
        const float xs[4] = {v.x, v.y, v.z, v.w};
        __nv_bfloat16 h[4], q[4];
        #pragma unroll
        for (int e = 0; e < 4; e++) {
            h[e] = __float2bfloat16(xs[e]);
            q[e] = __float2bfloat16(xs[e] * xs[e]);
        }
        int o = row * P0B + k4 * 2;
        *(uint32_t*)(sm + S_XH  + o)     = pk(h[0], h[1]);
        *(uint32_t*)(sm + S_XH  + o + 4) = pk(h[2], h[3]);
        *(uint32_t*)(sm + S_X2H + o)     = pk(q[0], q[1]);
        *(uint32_t*)(sm + S_X2H + o + 4) = pk(q[2], q[3]);
    }

    float accM1[4][4], accV1[4][4];
    #pragma unroll
    for (int b = 0; b < 4; b++)
        #pragma unroll
        for (int c = 0; c < 4; c++) { accM1[b][c] = 0.f; accV1[b][c] = 0.f; }

    for (int nc = 0; nc < 8; nc++) {
        // ---- issue W1[nc] (4 mats, 256 slots) ----------------------------------
        {
            int row = t >> 2, k16 = t & 3;
            size_t go = (size_t)row * R_DIM + nc * 32 + k16 * 8;
            uint32_t so = sb + S_W1 + row * P1B + k16 * 16;
            CP16(so,              (const char*)&g_w1mh[go]);
            CP16(so + W1_MAT,     (const char*)&g_w1ml[go]);
            CP16(so + 2 * W1_MAT, (const char*)&g_w1a1[go]);
            CP16(so + 3 * W1_MAT, (const char*)&g_w1vh[go]);
        }
        CP_COMMIT();
        CP_WAIT(1);                      // W0[nc] arrived (W1 may still fly)
        __syncthreads();                 // (1) W0/X visible; W1/L1A free

        // ---- layer0 MMA: warp tile 16(m) x 16(n) -------------------------------
        float aM[2][4], aV[2][4];
        #pragma unroll
        for (int b = 0; b < 2; b++)
            #pragma unroll
            for (int c = 0; c < 4; c++) { aM[b][c] = 0.f; aV[b][c] = 0.f; }

        #pragma unroll
        for (int ks = 0; ks < 8; ks++) {
            const int k = ks * 16;
            uint32_t Axh[4], A2h[4];
            {
                int ar = wm_ * 16 + lr + (sel & 1) * 8;
                int ac = k + (sel >> 1) * 8;
                uint32_t off = (uint32_t)(ar * P0B + ac * 2);
                LDSM4(Axh, sb + S_XH + off);
                LDSM4(A2h, sb + S_X2H + off);
            }
            uint32_t Bmh[4], Bml[4], Bvh[4];
            {
                int br = wn * 16 + lr + (sel >> 1) * 8;
                int bc = k + (sel & 1) * 8;
                uint32_t off = (uint32_t)(br * P0B + bc * 2);
                LDSM4(Bmh, sb + S_W0 + off);
                LDSM4(Bml, sb + S_W0 + W0_MAT + off);
                LDSM4(Bvh, sb + S_W0 + 2 * W0_MAT + off);
            }
            #pragma unroll
            for (int cq = 0; cq < 2; cq++) {
                int o2 = cq * 2;
                mma16816(aM[cq], Axh, &Bmh[o2]);
                mma16816(aM[cq], Axh, &Bml[o2]);
                mma16816(aV[cq], A2h, &Bvh[o2]);
            }
        }

        // ---- gate + convert into layer1 A buffers (mh / vh / m2h) ---------------
        #pragma unroll
        for (int cq = 0; cq < 2; cq++) {
            int klocal = wn * 16 + cq * 8 + 2 * (lane & 3);
            #pragma unroll
            for (int half = 0; half < 2; half++) {
                int lrow = wm_ * 16 + (lane >> 2) + half * 8;
                float m0 = aM[cq][half * 2 + 0];
                float m1 = aM[cq][half * 2 + 1];
                float v0 = aV[cq][half * 2 + 0];
                float v1 = aV[cq][half * 2 + 1];
                bool g0 = m0 > 0.f, g1 = m1 > 0.f;
                m0 = g0 ? m0 : 0.f;  v0 = g0 ? v0 : 0.f;
                m1 = g1 ? m1 : 0.f;  v1 = g1 ? v1 : 0.f;
                int o = lrow * P1B + klocal * 2;
                *(uint32_t*)(sm + S_L1MH + o) =
                    pk(__float2bfloat16(m0), __float2bfloat16(m1));
                *(uint32_t*)(sm + S_L1VH + o) =
                    pk(__float2bfloat16(v0), __float2bfloat16(v1));
                *(uint32_t*)(sm + S_L12H + o) =
                    pk(__float2bfloat16(m0 * m0), __float2bfloat16(m1 * m1));
            }
        }

        CP_WAIT(0);                      // W1[nc] fully arrived
        __syncthreads();                 // (2) L1A+W1 visible; W0 buffer free

        // ---- issue W0[nc+1] into the single buffer ------------------------------
        if (nc < 7) {
            #pragma unroll
            for (int it = 0; it < 2; it++) {
                int idx = t + it * NTHR;
                int r = idx >> 4, kk = idx & 15;
                size_t go = (size_t)((nc + 1) * 32 + r) * D_IN + kk * 8;
                uint32_t so = sb + S_W0 + r * P0B + kk * 16;
                CP16(so,              (const char*)&g_w0mh[go]);
                CP16(so + W0_MAT,     (const char*)&g_w0ml[go]);
                CP16(so + 2 * W0_MAT, (const char*)&g_w0vh[go]);
            }
        }
        CP_COMMIT();

        // ---- layer1 MMA: warp tile 16(m) x 32(n) --------------------------------
        #pragma unroll
        for (int ks = 0; ks < 2; ks++) {
            const int k = ks * 16;
            uint32_t Amh[4], Avh[4], A2m[4];
            {
                int ar = wm_ * 16 + lr + (sel & 1) * 8;
                int ac = k + (sel >> 1) * 8;
                uint32_t off = (uint32_t)(ar * P1B + ac * 2);
                LDSM4(Amh, sb + S_L1MH + off);
                LDSM4(Avh, sb + S_L1VH + off);
                LDSM4(A2m, sb + S_L12H + off);
            }
            #pragma unroll
            for (int p = 0; p < 2; p++) {
                uint32_t Bm[4], Bl[4], Ba[4], Bv[4];
                int br = wn * 32 + p * 16 + lr + (sel >> 1) * 8;
                int bc = k + (sel & 1) * 8;
                uint32_t off = (uint32_t)(br * P1B + bc * 2);
                LDSM4(Bm, sb + S_W1 + off);
                LDSM4(Bl, sb + S_W1 + W1_MAT + off);
                LDSM4(Ba, sb + S_W1 + 2 * W1_MAT + off);
                LDSM4(Bv, sb + S_W1 + 3 * W1_MAT + off);
                #pragma unroll
                for (int cq = 0; cq < 2; cq++) {
                    int cf = p * 2 + cq, o2 = cq * 2;
                    mma16816(accM1[cf], Amh, &Bm[o2]);
                    mma16816(accM1[cf], Amh, &Bl[o2]);
                    mma16816(accV1[cf], Avh, &Ba[o2]);
                    mma16816(accV1[cf], A2m, &Bv[o2]);
                }
            }
        }
        __syncthreads();                 // (3) W1/L1A free for next chunk
    }

    // ---- epilogue: inv-variance weighting into smem staging (overlays X) --------
    float* sInv  = (float*)(sm + S_SINV);
    float* sMinv = (float*)(sm + S_SMINV);
    #pragma unroll
    for (int cf = 0; cf < 4; cf++) {
        int col = wn * 32 + cf * 8 + 2 * (lane & 3);
        #pragma unroll
        for (int half = 0; half < 2; half++) {
            int lrow = wm_ * 16 + (lane >> 2) + half * 8;
            float m0 = accM1[cf][half * 2 + 0];
            float m1 = accM1[cf][half * 2 + 1];
            float V0 = fmaxf(accV1[cf][half * 2 + 0], EPS);
            float V1 = fmaxf(accV1[cf][half * 2 + 1], EPS);
            float i0 = 1.f / V0, i1 = 1.f / V1;
            sInv[lrow * 65 + col]      = i0;
            sInv[lrow * 65 + col + 1]  = i1;
            sMinv[lrow * 65 + col]     = m0 * i0;
            sMinv[lrow * 65 + col + 1] = m1 * i1;
        }
    }
    __syncthreads();

    // ---- block-level segmented reduce over sorted uids -> atomics ----------------
    const int* uids = (const int*)(sm + S_UID);
    int col = t & 63, grp = t >> 6;            // 4 groups x 16 rows
    float aI = 0.f, aM = 0.f;
    int cur = -1;
    for (int r0 = 0; r0 < 16; r0++) {
        int row = grp * 16 + r0;
        int uid = uids[row];
        if (uid != cur) {
            if (cur >= 0) {
                atomicAdd(&g_sum_inv[cur * D_OUT + col], aI);
                atomicAdd(&g_sum_minv[cur * D_OUT + col], aM);
            }
            cur = uid; aI = 0.f; aM = 0.f;
        }
        if (uid >= 0) {
            aI += sInv[row * 65 + col];
            aM += sMinv[row * 65 + col];
        }
    }
    if (cur >= 0) {
        atomicAdd(&g_sum_inv[cur * D_OUT + col], aI);
        atomicAdd(&g_sum_minv[cur * D_OUT + col], aM);
    }
}

// ---------------- finalize ----------------------------------------------------
__global__ __launch_bounds__(256) void finalize_kernel(float* __restrict__ out) {
    int id = blockIdx.x * 256 + threadIdx.x;
    if (id < U_DIM * D_OUT) {
        float var = 1.f / (g_sum_inv[id] + EPS);
        out[id]                 = g_sum_minv[id] * var;
        out[U_DIM * D_OUT + id] = var;
    }
}

// ---------------- launch -------------------------------------------------------
extern "C" void kernel_launch(void* const* d_in, const int* in_sizes, int n_in,
                              void* d_out, int out_size) {
    const float* X     = (const float*)d_in[0];
    const int*   X_idx = (const int*)d_in[1];
    const float* Wmu0  = (const float*)d_in[2];
    const float* Wlv0  = (const float*)d_in[3];
    const float* Wmu1  = (const float*)d_in[4];
    const float* Wlv1  = (const float*)d_in[5];
    float* out = (float*)d_out;
    (void)in_sizes; (void)n_in; (void)out_size;

    cudaFuncSetAttribute(fused_kernel, cudaFuncAttributeMaxDynamicSharedMemorySize,
                         SMEM_SZ);

    const int nBlocks = (N_ROWS + BM - 1) / BM;

    prep_kernel<<<(U_DIM * D_OUT + 255) / 256, 256>>>(Wmu0, Wlv0, Wmu1, Wlv1);
    fused_kernel<<<nBlocks, NTHR, SMEM_SZ>>>(X, X_idx);
    finalize_kernel<<<(U_DIM * D_OUT + 255) / 256, 256>>>(out);
}

// round 12
// speedup vs baseline: 1.1872x; 1.1872x over previous
#include <cuda_runtime.h>
#include <cuda_fp16.h>
#include <cstdint>
#include <cstddef>

#define N_ROWS 500000
#define D_IN   128
#define R_DIM  256
#define D_OUT  64
#define U_DIM  10000
#define EPS    1e-8f
#define BM     128         // rows per block
#define NTHR   256         // 8 warps

// ---------------- precomputed weights (fp16, [n][k] layout) -----------------
__device__ __half g_w0m[R_DIM * D_IN];            // Wmu0 (single fp16)
__device__ __half g_w0v[R_DIM * D_IN];            // exp(Wlv0)
__device__ __half g_w1mh[D_OUT * R_DIM];          // Wmu1 hi
__device__ __half g_w1ml[D_OUT * R_DIM];          // Wmu1 lo (fp16 residual)
__device__ __half g_w1a1[D_OUT * R_DIM];          // Wmu1^2 + exp(Wlv1)
__device__ __half g_w1vh[D_OUT * R_DIM];          // exp(Wlv1)
__device__ float g_sum_inv[U_DIM * D_OUT];
__device__ float g_sum_minv[U_DIM * D_OUT];

// ---------------- smem layout (bytes) ---------------------------------------
#define P0B 272
#define P1B 80
#define S_XH     0                     // 128*272 = 34816 (x fp16)
#define S_X2H    34816                 // x^2 fp16
#define S_W0     69632                 // 2 stages x 2 mats x 32*272
#define W0_STAGE 17408
#define W0_MAT   8704
#define S_W1     104448                // 4 mats x 64*80 = 20480
#define W1_MAT   5120
#define S_L1MH   124928                // 128*80 each
#define S_L1VH   135168
#define S_L12H   145408
#define S_UID    155648                // 128*4
#define SMEM_SZ  156160
#define S_SINV   0                     // staging overlays XH (post-GEMM)
#define S_SMINV  34816                 // overlays X2H

// ---------------- helpers ----------------------------------------------------
static __device__ __forceinline__ uint32_t smem_u32(const void* p) {
    uint32_t a;
    asm("{ .reg .u64 t; cvta.to.shared.u64 t, %1; cvt.u32.u64 %0, t; }"
        : "=r"(a) : "l"(p));
    return a;
}
#define LDSM4(R, addr) \
    asm volatile("ldmatrix.sync.aligned.m8n8.x4.shared.b16 {%0,%1,%2,%3}, [%4];" \
        : "=r"((R)[0]), "=r"((R)[1]), "=r"((R)[2]), "=r"((R)[3]) : "r"(addr))
#define CP16(s, g) \
    asm volatile("cp.async.cg.shared.global [%0], [%1], 16;" :: "r"(s), "l"(g))
#define CP_COMMIT() asm volatile("cp.async.commit_group;" ::: "memory")
#define CP_WAIT(N)  asm volatile("cp.async.wait_group %0;" :: "n"(N) : "memory")

static __device__ __forceinline__ void mma16816h(float* c, const uint32_t* a,
                                                 const uint32_t* b) {
    asm volatile("mma.sync.aligned.m16n8k16.row.col.f32.f16.f16.f32 "
                 "{%0,%1,%2,%3},{%4,%5,%6,%7},{%8,%9},{%0,%1,%2,%3};"
                 : "+f"(c[0]), "+f"(c[1]), "+f"(c[2]), "+f"(c[3])
                 : "r"(a[0]), "r"(a[1]), "r"(a[2]), "r"(a[3]),
                   "r"(b[0]), "r"(b[1]));
}
static __device__ __forceinline__ void split2h(float x, __half& h, __half& l) {
    h = __float2half(x);
    l = __float2half(x - __half2float(h));
}
static __device__ __forceinline__ uint32_t pkh(__half a, __half b) {
    return (uint32_t)__half_as_ushort(a) | ((uint32_t)__half_as_ushort(b) << 16);
}

// ---------------- prep -------------------------------------------------------
__global__ __launch_bounds__(256) void prep_kernel(const float* __restrict__ Wmu0,
                                                   const float* __restrict__ Wlv0,
                                                   const float* __restrict__ Wmu1,
                                                   const float* __restrict__ Wlv1) {
    int id = blockIdx.x * 256 + threadIdx.x;
    if (id < R_DIM * D_IN) {
        int n = id >> 7, k = id & 127;
        float wm = Wmu0[(size_t)k * R_DIM + n];
        float wv = expf(Wlv0[(size_t)k * R_DIM + n]);
        g_w0m[id] = __float2half(wm);
        g_w0v[id] = __float2half(wv);
    }
    if (id < D_OUT * R_DIM) {
        int n = id >> 8, k = id & 255;
        float wm = Wmu1[(size_t)k * D_OUT + n];
        float e  = expf(Wlv1[(size_t)k * D_OUT + n]);
        __half h, l;
        split2h(wm, h, l);
        g_w1mh[id] = h;
        g_w1ml[id] = l;
        g_w1a1[id] = __float2half(wm * wm + e);
        g_w1vh[id] = __float2half(e);
    }
    if (id < U_DIM * D_OUT) { g_sum_inv[id] = 0.f; g_sum_minv[id] = 0.f; }
}

// ============================================================================
// Fused kernel: 128 rows/block, 256 threads, warp grid 4(m) x 2(n).
// 8 weight chunks of 32; W0 double-buffered + cp.async pipelined. All fp16:
//   L0 M = x*w0m,         L0 V = x2*w0v,
//   L1 M = m*(w1mh+w1ml), L1 V = v*a1 + m2*w1v.
// ============================================================================
__global__ __launch_bounds__(NTHR, 1) void fused_kernel(const float* __restrict__ X,
                                                        const int* __restrict__ X_idx) {
    extern __shared__ char sm[];
    const uint32_t sb = smem_u32(sm);
    const int t = threadIdx.x, lane = t & 31, wid = t >> 5;
    const int wm_ = wid >> 1, wn = wid & 1;
    const int rowBase = blockIdx.x * BM;
    const int lr = lane & 7, sel = lane >> 3;

    // ---- prefetch W0[0] into stage 0 (512 slots = 32 rows x 16 units) --------
    #pragma unroll
    for (int it = 0; it < 2; it++) {
        int idx = t + it * NTHR;
        int r = idx >> 4, kk = idx & 15;
        uint32_t so = sb + S_W0 + r * P0B + kk * 16;
        size_t go = (size_t)r * D_IN + kk * 8;
        CP16(so,          (const char*)&g_w0m[go]);
        CP16(so + W0_MAT, (const char*)&g_w0v[go]);
    }
    CP_COMMIT();

    if (t < BM) {
        int r = rowBase + t;
        *(int*)(sm + S_UID + t * 4) = (r < N_ROWS) ? X_idx[r] : -1;
    }

    // ---- phase 0: X tile 128 x 128 -> x / x^2 (fp16) ---------------------------
    #pragma unroll
    for (int it = 0; it < 16; it++) {
        int idx = t + it * NTHR;
        int row = idx >> 5;
        int k4  = (idx & 31) * 4;
        float4 v = make_float4(0.f, 0.f, 0.f, 0.f);
        if (rowBase + row < N_ROWS)
            v = *(const float4*)&X[(size_t)(rowBase + row) * D_IN + k4];
        const float xs[4] = {v.x, v.y, v.z, v.w};
        __half h[4], q[4];
        #pragma unroll
        for (int e = 0; e < 4; e++) {
            h[e] = __float2half(xs[e]);
            q[e] = __float2half(xs[e] * xs[e]);
        }
        int o = row * P0B + k4 * 2;
        *(uint32_t*)(sm + S_XH  + o)     = pkh(h[0], h[1]);
        *(uint32_t*)(sm + S_XH  + o + 4) = pkh(h[2], h[3]);
        *(uint32_t*)(sm + S_X2H + o)     = pkh(q[0], q[1]);
        *(uint32_t*)(sm + S_X2H + o + 4) = pkh(q[2], q[3]);
    }

    float accM1[2][4][4], accV1[2][4][4];
    #pragma unroll
    for (int a = 0; a < 2; a++)
        #pragma unroll
        for (int b = 0; b < 4; b++)
            #pragma unroll
            for (int c = 0; c < 4; c++) { accM1[a][b][c] = 0.f; accV1[a][b][c] = 0.f; }

    for (int nc = 0; nc < 8; nc++) {
        // ---- issue W1[nc] (single buffer, 4 mats, 256 slots) ------------------
        {
            int row = t >> 2, k16 = t & 3;
            size_t go = (size_t)row * R_DIM + nc * 32 + k16 * 8;
            uint32_t so = sb + S_W1 + row * P1B + k16 * 16;
            CP16(so,              (const char*)&g_w1mh[go]);
            CP16(so + W1_MAT,     (const char*)&g_w1ml[go]);
            CP16(so + 2 * W1_MAT, (const char*)&g_w1a1[go]);
            CP16(so + 3 * W1_MAT, (const char*)&g_w1vh[go]);
        }
        CP_COMMIT();
        // ---- issue W0[nc+1] into stage (nc+1)&1 -------------------------------
        if (nc < 7) {
            uint32_t base = sb + S_W0 + ((nc + 1) & 1) * W0_STAGE;
            #pragma unroll
            for (int it = 0; it < 2; it++) {
                int idx = t + it * NTHR;
                int r = idx >> 4, kk = idx & 15;
                size_t go = (size_t)((nc + 1) * 32 + r) * D_IN + kk * 8;
                uint32_t so = base + r * P0B + kk * 16;
                CP16(so,          (const char*)&g_w0m[go]);
                CP16(so + W0_MAT, (const char*)&g_w0v[go]);
            }
        }
        CP_COMMIT();

        CP_WAIT(2);                      // W0[nc] arrived
        __syncthreads();

        // ---- layer0 MMA for this 32-col chunk (M 1-term, V 1-term) ------------
        const uint32_t w0b = sb + S_W0 + (nc & 1) * W0_STAGE;
        float aM[2][2][4], aV[2][2][4];
        #pragma unroll
        for (int a = 0; a < 2; a++)
            #pragma unroll
            for (int b = 0; b < 2; b++)
                #pragma unroll
                for (int c = 0; c < 4; c++) { aM[a][b][c] = 0.f; aV[a][b][c] = 0.f; }

        #pragma unroll
        for (int ks = 0; ks < 8; ks++) {
            const int k = ks * 16;
            uint32_t Axh[2][4], A2h[2][4];
            #pragma unroll
            for (int rf = 0; rf < 2; rf++) {
                int ar = wm_ * 32 + rf * 16 + lr + (sel & 1) * 8;
                int ac = k + (sel >> 1) * 8;
                uint32_t off = (uint32_t)(ar * P0B + ac * 2);
                LDSM4(Axh[rf], sb + S_XH + off);
                LDSM4(A2h[rf], sb + S_X2H + off);
            }
            uint32_t Bm[4], Bv[4];
            {
                int br = wn * 16 + lr + (sel >> 1) * 8;
                int bc = k + (sel & 1) * 8;
                uint32_t off = (uint32_t)(br * P0B + bc * 2);
                LDSM4(Bm, w0b + off);
                LDSM4(Bv, w0b + W0_MAT + off);
            }
            #pragma unroll
            for (int rf = 0; rf < 2; rf++) {
                #pragma unroll
                for (int cq = 0; cq < 2; cq++) {
                    int o2 = cq * 2;
                    mma16816h(aM[rf][cq], Axh[rf], &Bm[o2]);
                    mma16816h(aV[rf][cq], A2h[rf], &Bv[o2]);
                }
            }
        }

        // ---- gate + convert into layer1 A buffers (m / v / m^2, fp16) ----------
        #pragma unroll
        for (int rf = 0; rf < 2; rf++) {
            #pragma unroll
            for (int cq = 0; cq < 2; cq++) {
                int klocal = wn * 16 + cq * 8 + 2 * (lane & 3);
                #pragma unroll
                for (int half = 0; half < 2; half++) {
                    int lrow = wm_ * 32 + rf * 16 + (lane >> 2) + half * 8;
                    float m0 = aM[rf][cq][half * 2 + 0];
                    float m1 = aM[rf][cq][half * 2 + 1];
                    float v0 = aV[rf][cq][half * 2 + 0];
                    float v1 = aV[rf][cq][half * 2 + 1];
                    bool g0 = m0 > 0.f, g1 = m1 > 0.f;
                    m0 = g0 ? m0 : 0.f;  v0 = g0 ? v0 : 0.f;
                    m1 = g1 ? m1 : 0.f;  v1 = g1 ? v1 : 0.f;
                    int o = lrow * P1B + klocal * 2;
                    *(uint32_t*)(sm + S_L1MH + o) =
                        pkh(__float2half(m0), __float2half(m1));
                    *(uint32_t*)(sm + S_L1VH + o) =
                        pkh(__float2half(v0), __float2half(v1));
                    *(uint32_t*)(sm + S_L12H + o) =
                        pkh(__float2half(m0 * m0), __float2half(m1 * m1));
                }
            }
        }

        CP_WAIT(1);                      // W1[nc] arrived (W0[nc+1] may still fly)
        __syncthreads();

        // ---- layer1 MMA accumulate (M 2-term, V 2-term) -------------------------
        #pragma unroll
        for (int ks = 0; ks < 2; ks++) {
            const int k = ks * 16;
            uint32_t Amh[2][4], Avh[2][4], A2m[2][4];
            #pragma unroll
            for (int rf = 0; rf < 2; rf++) {
                int ar = wm_ * 32 + rf * 16 + lr + (sel & 1) * 8;
                int ac = k + (sel >> 1) * 8;
                uint32_t off = (uint32_t)(ar * P1B + ac * 2);
                LDSM4(Amh[rf], sb + S_L1MH + off);
                LDSM4(Avh[rf], sb + S_L1VH + off);
                LDSM4(A2m[rf], sb + S_L12H + off);
            }
            uint32_t Bm[2][4], Bl[2][4], Ba[2][4], Bv[2][4];
            #pragma unroll
            for (int p = 0; p < 2; p++) {
                int br = wn * 32 + p * 16 + lr + (sel >> 1) * 8;
                int bc = k + (sel & 1) * 8;
                uint32_t off = (uint32_t)(br * P1B + bc * 2);
                LDSM4(Bm[p], sb + S_W1 + off);
                LDSM4(Bl[p], sb + S_W1 + W1_MAT + off);
                LDSM4(Ba[p], sb + S_W1 + 2 * W1_MAT + off);
                LDSM4(Bv[p], sb + S_W1 + 3 * W1_MAT + off);
            }
            #pragma unroll
            for (int rf = 0; rf < 2; rf++) {
                #pragma unroll
                for (int p = 0; p < 2; p++) {
                    #pragma unroll
                    for (int cq = 0; cq < 2; cq++) {
                        int cf = p * 2 + cq, o2 = cq * 2;
                        mma16816h(accM1[rf][cf], Amh[rf], &Bm[p][o2]);
                        mma16816h(accM1[rf][cf], Amh[rf], &Bl[p][o2]);
                        mma16816h(accV1[rf][cf], Avh[rf], &Ba[p][o2]);
                        mma16816h(accV1[rf][cf], A2m[rf], &Bv[p][o2]);
                    }
                }
            }
        }
        __syncthreads();                 // W1 + L1A buffers free for next chunk
    }

    // ---- epilogue: inv-variance weighting into smem staging --------------------
    float* sInv  = (float*)(sm + S_SINV);
    float* sMinv = (float*)(sm + S_SMINV);
    #pragma unroll
    for (int rf = 0; rf < 2; rf++) {
        #pragma unroll
        for (int cf = 0; cf < 4; cf++) {
            int col = wn * 32 + cf * 8 + 2 * (lane & 3);
            #pragma unroll
            for (int half = 0; half < 2; half++) {
                int lrow = wm_ * 32 + rf * 16 + (lane >> 2) + half * 8;
                float m0 = accM1[rf][cf][half * 2 + 0];
                float m1 = accM1[rf][cf][half * 2 + 1];
                float V0 = fmaxf(accV1[rf][cf][half * 2 + 0], EPS);
                float V1 = fmaxf(accV1[rf][cf][half * 2 + 1], EPS);
                float i0 = 1.f / V0, i1 = 1.f / V1;
                sInv[lrow * 65 + col]      = i0;
                sInv[lrow * 65 + col + 1]  = i1;
                sMinv[lrow * 65 + col]     = m0 * i0;
                sMinv[lrow * 65 + col + 1] = m1 * i1;
            }
        }
    }
    __syncthreads();

    // ---- block-level segmented reduce over sorted uids -> atomics ---------------
    const int* uids = (const int*)(sm + S_UID);
    int col = t & 63, grp = t >> 6;            // 4 groups x 32 rows
    float aI = 0.f, aM = 0.f;
    int cur = -1;
    for (int r0 = 0; r0 < 32; r0++) {
        int row = grp * 32 + r0;
        int uid = uids[row];
        if (uid != cur) {
            if (cur >= 0) {
                atomicAdd(&g_sum_inv[cur * D_OUT + col], aI);
                atomicAdd(&g_sum_minv[cur * D_OUT + col], aM);
            }
            cur = uid; aI = 0.f; aM = 0.f;
        }
        if (uid >= 0) {
            aI += sInv[row * 65 + col];
            aM += sMinv[row * 65 + col];
        }
    }
    if (cur >= 0) {
        atomicAdd(&g_sum_inv[cur * D_OUT + col], aI);
        atomicAdd(&g_sum_minv[cur * D_OUT + col], aM);
    }
}

// ---------------- finalize ----------------------------------------------------
__global__ __launch_bounds__(256) void finalize_kernel(float* __restrict__ out) {
    int id = blockIdx.x * 256 + threadIdx.x;
    if (id < U_DIM * D_OUT) {
        float var = 1.f / (g_sum_inv[id] + EPS);
        out[id]                 = g_sum_minv[id] * var;
        out[U_DIM * D_OUT + id] = var;
    }
}

// ---------------- launch -------------------------------------------------------
extern "C" void kernel_launch(void* const* d_in, const int* in_sizes, int n_in,
                              void* d_out, int out_size) {
    const float* X     = (const float*)d_in[0];
    const int*   X_idx = (const int*)d_in[1];
    const float* Wmu0  = (const float*)d_in[2];
    const float* Wlv0  = (const float*)d_in[3];
    const float* Wmu1  = (const float*)d_in[4];
    const float* Wlv1  = (const float*)d_in[5];
    float* out = (float*)d_out;
    (void)in_sizes; (void)n_in; (void)out_size;

    cudaFuncSetAttribute(fused_kernel, cudaFuncAttributeMaxDynamicSharedMemorySize,
                         SMEM_SZ);

    const int nBlocks = (N_ROWS + BM - 1) / BM;

    prep_kernel<<<(U_DIM * D_OUT + 255) / 256, 256>>>(Wmu0, Wlv0, Wmu1, Wlv1);
    fused_kernel<<<nBlocks, NTHR, SMEM_SZ>>>(X, X_idx);
    finalize_kernel<<<(U_DIM * D_OUT + 255) / 256, 256>>>(out);
}

// round 13
// speedup vs baseline: 1.2786x; 1.0770x over previous
#include <cuda_runtime.h>
#include <cuda_fp16.h>
#include <cstdint>
#include <cstddef>

#define N_ROWS 500000
#define D_IN   128
#define R_DIM  256
#define D_OUT  64
#define U_DIM  10000
#define EPS    1e-8f
#define BM     128         // rows per block
#define NTHR   256         // 8 warps

// ---------------- precomputed weights (fp16, [n][k] layout) -----------------
__device__ __half g_w0m[R_DIM * D_IN];            // Wmu0
__device__ __half g_w0v[R_DIM * D_IN];            // exp(Wlv0)
__device__ __half g_w1m[D_OUT * R_DIM];           // Wmu1
__device__ __half g_w1a1[D_OUT * R_DIM];          // Wmu1^2 + exp(Wlv1)
__device__ __half g_w1vh[D_OUT * R_DIM];          // exp(Wlv1)
__device__ float g_sum_inv[U_DIM * D_OUT];
__device__ float g_sum_minv[U_DIM * D_OUT];

// ---------------- smem layout (bytes) ---------------------------------------
#define P0B 272
#define P1B 80
#define S_XH     0                     // 128*272 = 34816 (x fp16)
#define S_X2H    34816                 // x^2 fp16
#define S_W0     69632                 // 2 stages x 2 mats x 32*272
#define W0_STAGE 17408
#define W0_MAT   8704
#define S_W1     104448                // 3 mats x 64*80 = 15360
#define W1_MAT   5120
#define S_L1MH   119808                // 128*80 each
#define S_L1VH   130048
#define S_L12H   140288
#define S_UID    150528                // 128*4
#define SMEM_SZ  151040
#define S_SINV   0                     // staging overlays XH (post-GEMM)
#define S_SMINV  34816                 // overlays X2H

// ---------------- helpers ----------------------------------------------------
static __device__ __forceinline__ uint32_t smem_u32(const void* p) {
    uint32_t a;
    asm("{ .reg .u64 t; cvta.to.shared.u64 t, %1; cvt.u32.u64 %0, t; }"
        : "=r"(a) : "l"(p));
    return a;
}
#define LDSM4(R, addr) \
    asm volatile("ldmatrix.sync.aligned.m8n8.x4.shared.b16 {%0,%1,%2,%3}, [%4];" \
        : "=r"((R)[0]), "=r"((R)[1]), "=r"((R)[2]), "=r"((R)[3]) : "r"(addr))
#define CP16(s, g) \
    asm volatile("cp.async.cg.shared.global [%0], [%1], 16;" :: "r"(s), "l"(g))
#define CP_COMMIT() asm volatile("cp.async.commit_group;" ::: "memory")
#define CP_WAIT(N)  asm volatile("cp.async.wait_group %0;" :: "n"(N) : "memory")

static __device__ __forceinline__ void mma16816h(float* c, const uint32_t* a,
                                                 const uint32_t* b) {
    asm volatile("mma.sync.aligned.m16n8k16.row.col.f32.f16.f16.f32 "
                 "{%0,%1,%2,%3},{%4,%5,%6,%7},{%8,%9},{%0,%1,%2,%3};"
                 : "+f"(c[0]), "+f"(c[1]), "+f"(c[2]), "+f"(c[3])
                 : "r"(a[0]), "r"(a[1]), "r"(a[2]), "r"(a[3]),
                   "r"(b[0]), "r"(b[1]));
}
static __device__ __forceinline__ uint32_t pkh(__half a, __half b) {
    return (uint32_t)__half_as_ushort(a) | ((uint32_t)__half_as_ushort(b) << 16);
}

// ---------------- prep -------------------------------------------------------
__global__ __launch_bounds__(256) void prep_kernel(const float* __restrict__ Wmu0,
                                                   const float* __restrict__ Wlv0,
                                                   const float* __restrict__ Wmu1,
                                                   const float* __restrict__ Wlv1) {
    int id = blockIdx.x * 256 + threadIdx.x;
    if (id < R_DIM * D_IN) {
        int n = id >> 7, k = id & 127;
        float wm = Wmu0[(size_t)k * R_DIM + n];
        float wv = expf(Wlv0[(size_t)k * R_DIM + n]);
        g_w0m[id] = __float2half(wm);
        g_w0v[id] = __float2half(wv);
    }
    if (id < D_OUT * R_DIM) {
        int n = id >> 8, k = id & 255;
        float wm = Wmu1[(size_t)k * D_OUT + n];
        float e  = expf(Wlv1[(size_t)k * D_OUT + n]);
        g_w1m[id]  = __float2half(wm);
        g_w1a1[id] = __float2half(wm * wm + e);
        g_w1vh[id] = __float2half(e);
    }
    if (id < U_DIM * D_OUT) { g_sum_inv[id] = 0.f; g_sum_minv[id] = 0.f; }
}

// ============================================================================
// Fused kernel: 128 rows/block, 256 threads, warp grid 4(m) x 2(n).
// 8 weight chunks of 32; W0 double-buffered + cp.async pipelined. All fp16:
//   L0 M = x*w0m,  L0 V = x2*w0v,
//   L1 M = m*w1m,  L1 V = v*a1 + m2*w1v.
// ============================================================================
__global__ __launch_bounds__(NTHR, 1) void fused_kernel(const float* __restrict__ X,
                                                        const int* __restrict__ X_idx) {
    extern __shared__ char sm[];
    const uint32_t sb = smem_u32(sm);
    const int t = threadIdx.x, lane = t & 31, wid = t >> 5;
    const int wm_ = wid >> 1, wn = wid & 1;
    const int rowBase = blockIdx.x * BM;
    const int lr = lane & 7, sel = lane >> 3;

    // ---- prefetch W0[0] into stage 0 (512 slots = 32 rows x 16 units) --------
    #pragma unroll
    for (int it = 0; it < 2; it++) {
        int idx = t + it * NTHR;
        int r = idx >> 4, kk = idx & 15;
        uint32_t so = sb + S_W0 + r * P0B + kk * 16;
        size_t go = (size_t)r * D_IN + kk * 8;
        CP16(so,          (const char*)&g_w0m[go]);
        CP16(so + W0_MAT, (const char*)&g_w0v[go]);
    }
    CP_COMMIT();

    if (t < BM) {
        int r = rowBase + t;
        *(int*)(sm + S_UID + t * 4) = (r < N_ROWS) ? X_idx[r] : -1;
    }

    // ---- phase 0: X tile 128 x 128 -> x / x^2 (fp16) ---------------------------
    #pragma unroll
    for (int it = 0; it < 16; it++) {
        int idx = t + it * NTHR;
        int row = idx >> 5;
        int k4  = (idx & 31) * 4;
        float4 v = make_float4(0.f, 0.f, 0.f, 0.f);
        if (rowBase + row < N_ROWS)
            v = *(const float4*)&X[(size_t)(rowBase + row) * D_IN + k4];
        const float xs[4] = {v.x, v.y, v.z, v.w};
        __half h[4], q[4];
        #pragma unroll
        for (int e = 0; e < 4; e++) {
            h[e] = __float2half(xs[e]);
            q[e] = __float2half(xs[e] * xs[e]);
        }
        int o = row * P0B + k4 * 2;
        *(uint32_t*)(sm + S_XH  + o)     = pkh(h[0], h[1]);
        *(uint32_t*)(sm + S_XH  + o + 4) = pkh(h[2], h[3]);
        *(uint32_t*)(sm + S_X2H + o)     = pkh(q[0], q[1]);
        *(uint32_t*)(sm + S_X2H + o + 4) = pkh(q[2], q[3]);
    }

    float accM1[2][4][4], accV1[2][4][4];
    #pragma unroll
    for (int a = 0; a < 2; a++)
        #pragma unroll
        for (int b = 0; b < 4; b++)
            #pragma unroll
            for (int c = 0; c < 4; c++) { accM1[a][b][c] = 0.f; accV1[a][b][c] = 0.f; }

    for (int nc = 0; nc < 8; nc++) {
        // ---- issue W1[nc] (single buffer, 3 mats, 256 slots) ------------------
        {
            int row = t >> 2, k16 = t & 3;
            size_t go = (size_t)row * R_DIM + nc * 32 + k16 * 8;
            uint32_t so = sb + S_W1 + row * P1B + k16 * 16;
            CP16(so,              (const char*)&g_w1m[go]);
            CP16(so + W1_MAT,     (const char*)&g_w1a1[go]);
            CP16(so + 2 * W1_MAT, (const char*)&g_w1vh[go]);
        }
        CP_COMMIT();
        // ---- issue W0[nc+1] into stage (nc+1)&1 -------------------------------
        if (nc < 7) {
            uint32_t base = sb + S_W0 + ((nc + 1) & 1) * W0_STAGE;
            #pragma unroll
            for (int it = 0; it < 2; it++) {
                int idx = t + it * NTHR;
                int r = idx >> 4, kk = idx & 15;
                size_t go = (size_t)((nc + 1) * 32 + r) * D_IN + kk * 8;
                uint32_t so = base + r * P0B + kk * 16;
                CP16(so,          (const char*)&g_w0m[go]);
                CP16(so + W0_MAT, (const char*)&g_w0v[go]);
            }
        }
        CP_COMMIT();

        CP_WAIT(2);                      // W0[nc] arrived
        __syncthreads();

        // ---- layer0 MMA for this 32-col chunk (M 1-term, V 1-term) ------------
        const uint32_t w0b = sb + S_W0 + (nc & 1) * W0_STAGE;
        float aM[2][2][4], aV[2][2][4];
        #pragma unroll
        for (int a = 0; a < 2; a++)
            #pragma unroll
            for (int b = 0; b < 2; b++)
                #pragma unroll
                for (int c = 0; c < 4; c++) { aM[a][b][c] = 0.f; aV[a][b][c] = 0.f; }

        #pragma unroll
        for (int ks = 0; ks < 8; ks++) {
            const int k = ks * 16;
            uint32_t Axh[2][4], A2h[2][4];
            #pragma unroll
            for (int rf = 0; rf < 2; rf++) {
                int ar = wm_ * 32 + rf * 16 + lr + (sel & 1) * 8;
                int ac = k + (sel >> 1) * 8;
                uint32_t off = (uint32_t)(ar * P0B + ac * 2);
                LDSM4(Axh[rf], sb + S_XH + off);
                LDSM4(A2h[rf], sb + S_X2H + off);
            }
            uint32_t Bm[4], Bv[4];
            {
                int br = wn * 16 + lr + (sel >> 1) * 8;
                int bc = k + (sel & 1) * 8;
                uint32_t off = (uint32_t)(br * P0B + bc * 2);
                LDSM4(Bm, w0b + off);
                LDSM4(Bv, w0b + W0_MAT + off);
            }
            #pragma unroll
            for (int rf = 0; rf < 2; rf++) {
                #pragma unroll
                for (int cq = 0; cq < 2; cq++) {
                    int o2 = cq * 2;
                    mma16816h(aM[rf][cq], Axh[rf], &Bm[o2]);
                    mma16816h(aV[rf][cq], A2h[rf], &Bv[o2]);
                }
            }
        }

        // ---- gate + convert into layer1 A buffers (m / v / m^2, fp16) ----------
        #pragma unroll
        for (int rf = 0; rf < 2; rf++) {
            #pragma unroll
            for (int cq = 0; cq < 2; cq++) {
                int klocal = wn * 16 + cq * 8 + 2 * (lane & 3);
                #pragma unroll
                for (int half = 0; half < 2; half++) {
                    int lrow = wm_ * 32 + rf * 16 + (lane >> 2) + half * 8;
                    float m0 = aM[rf][cq][half * 2 + 0];
                    float m1 = aM[rf][cq][half * 2 + 1];
                    float v0 = aV[rf][cq][half * 2 + 0];
                    float v1 = aV[rf][cq][half * 2 + 1];
                    bool g0 = m0 > 0.f, g1 = m1 > 0.f;
                    m0 = g0 ? m0 : 0.f;  v0 = g0 ? v0 : 0.f;
                    m1 = g1 ? m1 : 0.f;  v1 = g1 ? v1 : 0.f;
                    int o = lrow * P1B + klocal * 2;
                    *(uint32_t*)(sm + S_L1MH + o) =
                        pkh(__float2half(m0), __float2half(m1));
                    *(uint32_t*)(sm + S_L1VH + o) =
                        pkh(__float2half(v0), __float2half(v1));
                    *(uint32_t*)(sm + S_L12H + o) =
                        pkh(__float2half(m0 * m0), __float2half(m1 * m1));
                }
            }
        }

        CP_WAIT(1);                      // W1[nc] arrived (W0[nc+1] may still fly)
        __syncthreads();

        // ---- layer1 MMA accumulate (M 1-term, V 2-term) -------------------------
        #pragma unroll
        for (int ks = 0; ks < 2; ks++) {
            const int k = ks * 16;
            uint32_t Amh[2][4], Avh[2][4], A2m[2][4];
            #pragma unroll
            for (int rf = 0; rf < 2; rf++) {
                int ar = wm_ * 32 + rf * 16 + lr + (sel & 1) * 8;
                int ac = k + (sel >> 1) * 8;
                uint32_t off = (uint32_t)(ar * P1B + ac * 2);
                LDSM4(Amh[rf], sb + S_L1MH + off);
                LDSM4(Avh[rf], sb + S_L1VH + off);
                LDSM4(A2m[rf], sb + S_L12H + off);
            }
            uint32_t Bm[2][4], Ba[2][4], Bv[2][4];
            #pragma unroll
            for (int p = 0; p < 2; p++) {
                int br = wn * 32 + p * 16 + lr + (sel >> 1) * 8;
                int bc = k + (sel & 1) * 8;
                uint32_t off = (uint32_t)(br * P1B + bc * 2);
                LDSM4(Bm[p], sb + S_W1 + off);
                LDSM4(Ba[p], sb + S_W1 + W1_MAT + off);
                LDSM4(Bv[p], sb + S_W1 + 2 * W1_MAT + off);
            }
            #pragma unroll
            for (int rf = 0; rf < 2; rf++) {
                #pragma unroll
                for (int p = 0; p < 2; p++) {
                    #pragma unroll
                    for (int cq = 0; cq < 2; cq++) {
                        int cf = p * 2 + cq, o2 = cq * 2;
                        mma16816h(accM1[rf][cf], Amh[rf], &Bm[p][o2]);
                        mma16816h(accV1[rf][cf], Avh[rf], &Ba[p][o2]);
                        mma16816h(accV1[rf][cf], A2m[rf], &Bv[p][o2]);
                    }
                }
            }
        }
        __syncthreads();                 // W1 + L1A buffers free for next chunk
    }

    // ---- epilogue: inv-variance weighting into smem staging --------------------
    float* sInv  = (float*)(sm + S_SINV);
    float* sMinv = (float*)(sm + S_SMINV);
    #pragma unroll
    for (int rf = 0; rf < 2; rf++) {
        #pragma unroll
        for (int cf = 0; cf < 4; cf++) {
            int col = wn * 32 + cf * 8 + 2 * (lane & 3);
            #pragma unroll
            for (int half = 0; half < 2; half++) {
                int lrow = wm_ * 32 + rf * 16 + (lane >> 2) + half * 8;
                float m0 = accM1[rf][cf][half * 2 + 0];
                float m1 = accM1[rf][cf][half * 2 + 1];
                float V0 = fmaxf(accV1[rf][cf][half * 2 + 0], EPS);
                float V1 = fmaxf(accV1[rf][cf][half * 2 + 1], EPS);
                float i0 = 1.f / V0, i1 = 1.f / V1;
                sInv[lrow * 65 + col]      = i0;
                sInv[lrow * 65 + col + 1]  = i1;
                sMinv[lrow * 65 + col]     = m0 * i0;
                sMinv[lrow * 65 + col + 1] = m1 * i1;
            }
        }
    }
    __syncthreads();

    // ---- block-level segmented reduce over sorted uids -> atomics ---------------
    const int* uids = (const int*)(sm + S_UID);
    int col = t & 63, grp = t >> 6;            // 4 groups x 32 rows
    float aI = 0.f, aM = 0.f;
    int cur = -1;
    for (int r0 = 0; r0 < 32; r0++) {
        int row = grp * 32 + r0;
        int uid = uids[row];
        if (uid != cur) {
            if (cur >= 0) {
                atomicAdd(&g_sum_inv[cur * D_OUT + col], aI);
                atomicAdd(&g_sum_minv[cur * D_OUT + col], aM);
            }
            cur = uid; aI = 0.f; aM = 0.f;
        }
        if (uid >= 0) {
            aI += sInv[row * 65 + col];
            aM += sMinv[row * 65 + col];
        }
    }
    if (cur >= 0) {
        atomicAdd(&g_sum_inv[cur * D_OUT + col], aI);
        atomicAdd(&g_sum_minv[cur * D_OUT + col], aM);
    }
}

// ---------------- finalize ----------------------------------------------------
__global__ __launch_bounds__(256) void finalize_kernel(float* __restrict__ out) {
    int id = blockIdx.x * 256 + threadIdx.x;
    if (id < U_DIM * D_OUT) {
        float var = 1.f / (g_sum_inv[id] + EPS);
        out[id]                 = g_sum_minv[id] * var;
        out[U_DIM * D_OUT + id] = var;
    }
}

// ---------------- launch -------------------------------------------------------
extern "C" void kernel_launch(void* const* d_in, const int* in_sizes, int n_in,
                              void* d_out, int out_size) {
    const float* X     = (const float*)d_in[0];
    const int*   X_idx = (const int*)d_in[1];
    const float* Wmu0  = (const float*)d_in[2];
    const float* Wlv0  = (const float*)d_in[3];
    const float* Wmu1  = (const float*)d_in[4];
    const float* Wlv1  = (const float*)d_in[5];
    float* out = (float*)d_out;
    (void)in_sizes; (void)n_in; (void)out_size;

    cudaFuncSetAttribute(fused_kernel, cudaFuncAttributeMaxDynamicSharedMemorySize,
                         SMEM_SZ);

    const int nBlocks = (N_ROWS + BM - 1) / BM;

    prep_kernel<<<(U_DIM * D_OUT + 255) / 256, 256>>>(Wmu0, Wlv0, Wmu1, Wlv1);
    fused_kernel<<<nBlocks, NTHR, SMEM_SZ>>>(X, X_idx);
    finalize_kernel<<<(U_DIM * D_OUT + 255) / 256, 256>>>(out);
}

// round 14
// speedup vs baseline: 1.4286x; 1.1173x over previous
#include <cuda_runtime.h>
#include <cuda_fp16.h>
#include <cstdint>
#include <cstddef>

#define N_ROWS 500000
#define D_IN   128
#define R_DIM  256
#define D_OUT  64
#define U_DIM  10000
#define EPS    1e-8f
#define BM     128         // rows per block
#define NTHR   256         // 8 warps, each owns 16 rows

// ---------------- precomputed weights (fp16, [n][k] layout) -----------------
__device__ __half g_w0m[R_DIM * D_IN];            // Wmu0
__device__ __half g_w0v[R_DIM * D_IN];            // exp(Wlv0)
__device__ __half g_w1m[D_OUT * R_DIM];           // Wmu1
__device__ __half g_w1a1[D_OUT * R_DIM];          // Wmu1^2 + exp(Wlv1)
__device__ __half g_w1vh[D_OUT * R_DIM];          // exp(Wlv1)
__device__ float g_sum_inv[U_DIM * D_OUT];
__device__ float g_sum_minv[U_DIM * D_OUT];

// ---------------- smem layout (bytes) ---------------------------------------
#define P0B 272
#define P1B 80
#define S_XH     0                     // 128*272 = 34816 (x fp16)
#define S_X2H    34816                 // x^2 fp16
#define S_W0     69632                 // 2 stages x 2 mats x 32*272
#define W0_STAGE 17408
#define W0_MAT   8704
#define S_W1     104448                // 2 stages x 3 mats x 64*80
#define W1_STAGE 15360
#define W1_MAT   5120
#define S_UID    135168                // 128*4
#define SMEM_SZ  135680
#define S_SINV   0                     // staging overlays XH (post-GEMM)
#define S_SMINV  34816                 // overlays X2H

// ---------------- helpers ----------------------------------------------------
static __device__ __forceinline__ uint32_t smem_u32(const void* p) {
    uint32_t a;
    asm("{ .reg .u64 t; cvta.to.shared.u64 t, %1; cvt.u32.u64 %0, t; }"
        : "=r"(a) : "l"(p));
    return a;
}
#define LDSM4(R, addr) \
    asm volatile("ldmatrix.sync.aligned.m8n8.x4.shared.b16 {%0,%1,%2,%3}, [%4];" \
        : "=r"((R)[0]), "=r"((R)[1]), "=r"((R)[2]), "=r"((R)[3]) : "r"(addr))
#define CP16(s, g) \
    asm volatile("cp.async.cg.shared.global [%0], [%1], 16;" :: "r"(s), "l"(g))
#define CP_COMMIT() asm volatile("cp.async.commit_group;" ::: "memory")
#define CP_WAIT(N)  asm volatile("cp.async.wait_group %0;" :: "n"(N) : "memory")

static __device__ __forceinline__ void mma16816h(float* c, const uint32_t* a,
                                                 const uint32_t* b) {
    asm volatile("mma.sync.aligned.m16n8k16.row.col.f32.f16.f16.f32 "
                 "{%0,%1,%2,%3},{%4,%5,%6,%7},{%8,%9},{%0,%1,%2,%3};"
                 : "+f"(c[0]), "+f"(c[1]), "+f"(c[2]), "+f"(c[3])
                 : "r"(a[0]), "r"(a[1]), "r"(a[2]), "r"(a[3]),
                   "r"(b[0]), "r"(b[1]));
}
static __device__ __forceinline__ uint32_t pkh(__half a, __half b) {
    return (uint32_t)__half_as_ushort(a) | ((uint32_t)__half_as_ushort(b) << 16);
}
static __device__ __forceinline__ uint32_t pkf(float a, float b) {
    return pkh(__float2half(a), __float2half(b));
}

// ---------------- prep -------------------------------------------------------
__global__ __launch_bounds__(256) void prep_kernel(const float* __restrict__ Wmu0,
                                                   const float* __restrict__ Wlv0,
                                                   const float* __restrict__ Wmu1,
                                                   const float* __restrict__ Wlv1) {
    int id = blockIdx.x * 256 + threadIdx.x;
    if (id < R_DIM * D_IN) {
        int n = id >> 7, k = id & 127;
        float wm = Wmu0[(size_t)k * R_DIM + n];
        float wv = expf(Wlv0[(size_t)k * R_DIM + n]);
        g_w0m[id] = __float2half(wm);
        g_w0v[id] = __float2half(wv);
    }
    if (id < D_OUT * R_DIM) {
        int n = id >> 8, k = id & 255;
        float wm = Wmu1[(size_t)k * D_OUT + n];
        float e  = expf(Wlv1[(size_t)k * D_OUT + n]);
        g_w1m[id]  = __float2half(wm);
        g_w1a1[id] = __float2half(wm * wm + e);
        g_w1vh[id] = __float2half(e);
    }
    if (id < U_DIM * D_OUT) { g_sum_inv[id] = 0.f; g_sum_minv[id] = 0.f; }
}

// ============================================================================
// Fused kernel: 128 rows/block, 256 threads, 8 warps x 16 rows each.
// Layer0 output stays in registers; its C-fragments are repacked as the A
// operands of layer1 (flash-attention style) — no intermediate smem staging.
// W0 and W1 both double-buffered; ONE commit group + ONE barrier per chunk.
//   L0 M = x*w0m,  L0 V = x2*w0v,
//   L1 M = m*w1m,  L1 V = v*a1 + m2*w1v.
// ============================================================================
__global__ __launch_bounds__(NTHR, 1) void fused_kernel(const float* __restrict__ X,
                                                        const int* __restrict__ X_idx) {
    extern __shared__ char sm[];
    const uint32_t sb = smem_u32(sm);
    const int t = threadIdx.x, lane = t & 31, wid = t >> 5;
    const int rowBase = blockIdx.x * BM;
    const int lr = lane & 7, sel = lane >> 3;

    // ---- prologue: prefetch W0[0] + W1[0] into stage 0, one group ------------
    #pragma unroll
    for (int it = 0; it < 2; it++) {
        int idx = t + it * NTHR;
        int r = idx >> 4, kk = idx & 15;
        uint32_t so = sb + S_W0 + r * P0B + kk * 16;
        size_t go = (size_t)r * D_IN + kk * 8;
        CP16(so,          (const char*)&g_w0m[go]);
        CP16(so + W0_MAT, (const char*)&g_w0v[go]);
    }
    {
        int row = t >> 2, k16 = t & 3;
        size_t go = (size_t)row * R_DIM + k16 * 8;
        uint32_t so = sb + S_W1 + row * P1B + k16 * 16;
        CP16(so,              (const char*)&g_w1m[go]);
        CP16(so + W1_MAT,     (const char*)&g_w1a1[go]);
        CP16(so + 2 * W1_MAT, (const char*)&g_w1vh[go]);
    }
    CP_COMMIT();

    if (t < BM) {
        int r = rowBase + t;
        *(int*)(sm + S_UID + t * 4) = (r < N_ROWS) ? X_idx[r] : -1;
    }

    // ---- phase 0: X tile 128 x 128 -> x / x^2 (fp16) ---------------------------
    #pragma unroll
    for (int it = 0; it < 16; it++) {
        int idx = t + it * NTHR;
        int row = idx >> 5;
        int k4  = (idx & 31) * 4;
        float4 v = make_float4(0.f, 0.f, 0.f, 0.f);
        if (rowBase + row < N_ROWS)
            v = *(const float4*)&X[(size_t)(rowBase + row) * D_IN + k4];
        int o = row * P0B + k4 * 2;
        *(uint32_t*)(sm + S_XH  + o)     = pkf(v.x, v.y);
        *(uint32_t*)(sm + S_XH  + o + 4) = pkf(v.z, v.w);
        *(uint32_t*)(sm + S_X2H + o)     = pkf(v.x * v.x, v.y * v.y);
        *(uint32_t*)(sm + S_X2H + o + 4) = pkf(v.z * v.z, v.w * v.w);
    }

    // layer1 accumulators: 8 n8-tiles x 4 (rows wid*16+lane/4+{0,8}, 64 cols)
    float acc1M[8][4], acc1V[8][4];
    #pragma unroll
    for (int b = 0; b < 8; b++)
        #pragma unroll
        for (int c = 0; c < 4; c++) { acc1M[b][c] = 0.f; acc1V[b][c] = 0.f; }

    for (int nc = 0; nc < 8; nc++) {
        CP_WAIT(0);                      // W0[nc] + W1[nc] arrived
        __syncthreads();                 // visible to all; prev-chunk reads done

        // ---- issue W0[nc+1] + W1[nc+1] into stage (nc+1)&1, one group ----------
        if (nc < 7) {
            uint32_t b0 = sb + S_W0 + ((nc + 1) & 1) * W0_STAGE;
            #pragma unroll
            for (int it = 0; it < 2; it++) {
                int idx = t + it * NTHR;
                int r = idx >> 4, kk = idx & 15;
                size_t go = (size_t)((nc + 1) * 32 + r) * D_IN + kk * 8;
                uint32_t so = b0 + r * P0B + kk * 16;
                CP16(so,          (const char*)&g_w0m[go]);
                CP16(so + W0_MAT, (const char*)&g_w0v[go]);
            }
            uint32_t b1 = sb + S_W1 + ((nc + 1) & 1) * W1_STAGE;
            int row = t >> 2, k16 = t & 3;
            size_t go = (size_t)row * R_DIM + (nc + 1) * 32 + k16 * 8;
            uint32_t so = b1 + row * P1B + k16 * 16;
            CP16(so,              (const char*)&g_w1m[go]);
            CP16(so + W1_MAT,     (const char*)&g_w1a1[go]);
            CP16(so + 2 * W1_MAT, (const char*)&g_w1vh[go]);
        }
        CP_COMMIT();

        const uint32_t w0b = sb + S_W0 + (nc & 1) * W0_STAGE;
        const uint32_t w1b = sb + S_W1 + (nc & 1) * W1_STAGE;

        // ---- layer0: warp tile 16(m) x 32(n), K=128 -----------------------------
        float a0M[4][4], a0V[4][4];
        #pragma unroll
        for (int b = 0; b < 4; b++)
            #pragma unroll
            for (int c = 0; c < 4; c++) { a0M[b][c] = 0.f; a0V[b][c] = 0.f; }

        #pragma unroll
        for (int ks = 0; ks < 8; ks++) {
            const int k = ks * 16;
            uint32_t Ax[4], A2[4];
            {
                int ar = wid * 16 + lr + (sel & 1) * 8;
                int ac = k + (sel >> 1) * 8;
                uint32_t off = (uint32_t)(ar * P0B + ac * 2);
                LDSM4(Ax, sb + S_XH + off);
                LDSM4(A2, sb + S_X2H + off);
            }
            #pragma unroll
            for (int g = 0; g < 2; g++) {
                uint32_t Bm[4], Bv[4];
                int br = g * 16 + lr + (sel >> 1) * 8;
                int bc = k + (sel & 1) * 8;
                uint32_t off = (uint32_t)(br * P0B + bc * 2);
                LDSM4(Bm, w0b + off);
                LDSM4(Bv, w0b + W0_MAT + off);
                #pragma unroll
                for (int q = 0; q < 2; q++) {
                    int n8 = g * 2 + q;
                    mma16816h(a0M[n8], Ax, &Bm[q * 2]);
                    mma16816h(a0V[n8], A2, &Bv[q * 2]);
                }
            }
        }

        // ---- gate + square + pack C-fragments into layer1 A-fragments ----------
        uint32_t Am[2][4], Av[2][4], A2m[2][4];   // [ko(k16)][a0..a3]
        #pragma unroll
        for (int n8 = 0; n8 < 4; n8++) {
            float gm[4], gv[4];
            #pragma unroll
            for (int e = 0; e < 4; e++) {
                float m = a0M[n8][e];
                bool g = m > 0.f;
                gm[e] = g ? m : 0.f;
                gv[e] = g ? a0V[n8][e] : 0.f;
            }
            int ko = n8 >> 1, hi = (n8 & 1) * 2;
            Am[ko][hi]      = pkf(gm[0], gm[1]);
            Am[ko][hi + 1]  = pkf(gm[2], gm[3]);
            Av[ko][hi]      = pkf(gv[0], gv[1]);
            Av[ko][hi + 1]  = pkf(gv[2], gv[3]);
            A2m[ko][hi]     = pkf(gm[0] * gm[0], gm[1] * gm[1]);
            A2m[ko][hi + 1] = pkf(gm[2] * gm[2], gm[3] * gm[3]);
        }

        // ---- layer1: warp tile 16(m) x 64(n), K=32 (A in registers) ------------
        #pragma unroll
        for (int ko = 0; ko < 2; ko++) {
            #pragma unroll
            for (int g = 0; g < 4; g++) {
                uint32_t Bm[4], Ba[4], Bv[4];
                int br = g * 16 + lr + (sel >> 1) * 8;
                int bc = ko * 16 + (sel & 1) * 8;
                uint32_t off = (uint32_t)(br * P1B + bc * 2);
                LDSM4(Bm, w1b + off);
                LDSM4(Ba, w1b + W1_MAT + off);
                LDSM4(Bv, w1b + 2 * W1_MAT + off);
                #pragma unroll
                for (int q = 0; q < 2; q++) {
                    int n8 = g * 2 + q;
                    mma16816h(acc1M[n8], Am[ko], &Bm[q * 2]);
                    mma16816h(acc1V[n8], Av[ko], &Ba[q * 2]);
                    mma16816h(acc1V[n8], A2m[ko], &Bv[q * 2]);
                }
            }
        }
    }

    __syncthreads();                     // all X reads done before staging overlay

    // ---- epilogue: inv-variance weighting into smem staging --------------------
    float* sInv  = (float*)(sm + S_SINV);
    float* sMinv = (float*)(sm + S_SMINV);
    #pragma unroll
    for (int n8 = 0; n8 < 8; n8++) {
        int col = n8 * 8 + 2 * (lane & 3);
        #pragma unroll
        for (int half = 0; half < 2; half++) {
            int lrow = wid * 16 + (lane >> 2) + half * 8;
            float m0 = acc1M[n8][half * 2 + 0];
            float m1 = acc1M[n8][half * 2 + 1];
            float V0 = fmaxf(acc1V[n8][half * 2 + 0], EPS);
            float V1 = fmaxf(acc1V[n8][half * 2 + 1], EPS);
            float i0 = 1.f / V0, i1 = 1.f / V1;
            sInv[lrow * 65 + col]      = i0;
            sInv[lrow * 65 + col + 1]  = i1;
            sMinv[lrow * 65 + col]     = m0 * i0;
            sMinv[lrow * 65 + col + 1] = m1 * i1;
        }
    }
    __syncthreads();

    // ---- block-level segmented reduce over sorted uids -> atomics ---------------
    const int* uids = (const int*)(sm + S_UID);
    int col = t & 63, grp = t >> 6;            // 4 groups x 32 rows
    float aI = 0.f, aM = 0.f;
    int cur = -1;
    for (int r0 = 0; r0 < 32; r0++) {
        int row = grp * 32 + r0;
        int uid = uids[row];
        if (uid != cur) {
            if (cur >= 0) {
                atomicAdd(&g_sum_inv[cur * D_OUT + col], aI);
                atomicAdd(&g_sum_minv[cur * D_OUT + col], aM);
            }
            cur = uid; aI = 0.f; aM = 0.f;
        }
        if (uid >= 0) {
            aI += sInv[row * 65 + col];
            aM += sMinv[row * 65 + col];
        }
    }
    if (cur >= 0) {
        atomicAdd(&g_sum_inv[cur * D_OUT + col], aI);
        atomicAdd(&g_sum_minv[cur * D_OUT + col], aM);
    }
}

// ---------------- finalize ----------------------------------------------------
__global__ __launch_bounds__(256) void finalize_kernel(float* __restrict__ out) {
    int id = blockIdx.x * 256 + threadIdx.x;
    if (id < U_DIM * D_OUT) {
        float var = 1.f / (g_sum_inv[id] + EPS);
        out[id]                 = g_sum_minv[id] * var;
        out[U_DIM * D_OUT + id] = var;
    }
}

// ---------------- launch -------------------------------------------------------
extern "C" void kernel_launch(void* const* d_in, const int* in_sizes, int n_in,
                              void* d_out, int out_size) {
    const float* X     = (const float*)d_in[0];
    const int*   X_idx = (const int*)d_in[1];
    const float* Wmu0  = (const float*)d_in[2];
    const float* Wlv0  = (const float*)d_in[3];
    const float* Wmu1  = (const float*)d_in[4];
    const float* Wlv1  = (const float*)d_in[5];
    float* out = (float*)d_out;
    (void)in_sizes; (void)n_in; (void)out_size;

    cudaFuncSetAttribute(fused_kernel, cudaFuncAttributeMaxDynamicSharedMemorySize,
                         SMEM_SZ);

    const int nBlocks = (N_ROWS + BM - 1) / BM;

    prep_kernel<<<(U_DIM * D_OUT + 255) / 256, 256>>>(Wmu0, Wlv0, Wmu1, Wlv1);
    fused_kernel<<<nBlocks, NTHR, SMEM_SZ>>>(X, X_idx);
    finalize_kernel<<<(U_DIM * D_OUT + 255) / 256, 256>>>(out);
}

// round 15
// speedup vs baseline: 1.5602x; 1.0921x over previous
#include <cuda_runtime.h>
#include <cuda_fp16.h>
#include <cstdint>
#include <cstddef>

#define N_ROWS 500000
#define D_IN   128
#define R_DIM  256
#define D_OUT  64
#define U_DIM  10000
#define EPS    1e-8f
#define BM     128         // rows per block
#define NTHR   256         // 8 warps, each owns 16 rows

// ---------------- precomputed weights (fp16, [n][k] layout) -----------------
__device__ __half g_w0m[R_DIM * D_IN];            // Wmu0
__device__ __half g_w0v[R_DIM * D_IN];            // exp(Wlv0)
__device__ __half g_w1m[D_OUT * R_DIM];           // Wmu1
__device__ __half g_w1a1[D_OUT * R_DIM];          // Wmu1^2 + exp(Wlv1)
__device__ __half g_w1vh[D_OUT * R_DIM];          // exp(Wlv1)
__device__ float g_sum_inv[U_DIM * D_OUT];
__device__ float g_sum_minv[U_DIM * D_OUT];

// ---------------- smem layout (bytes) ---------------------------------------
#define P0B 272
#define P1B 80
#define S_XH     0                     // 128*272 = 34816 (x fp16)
#define S_W0     34816                 // 2 stages x 2 mats x 32*272
#define W0_STAGE 17408
#define W0_MAT   8704
#define S_W1     69632                 // 2 stages x 3 mats x 64*80
#define W1_STAGE 15360
#define W1_MAT   5120
#define S_UID    100352                // 128*4
#define SMEM_SZ  100864
#define S_SINV   0                     // staging overlays XH (post-GEMM)
#define S_SMINV  34816                 // overlays W0 stages (dead post-GEMM)

// ---------------- helpers ----------------------------------------------------
static __device__ __forceinline__ uint32_t smem_u32(const void* p) {
    uint32_t a;
    asm("{ .reg .u64 t; cvta.to.shared.u64 t, %1; cvt.u32.u64 %0, t; }"
        : "=r"(a) : "l"(p));
    return a;
}
#define LDSM4(R, addr) \
    asm volatile("ldmatrix.sync.aligned.m8n8.x4.shared.b16 {%0,%1,%2,%3}, [%4];" \
        : "=r"((R)[0]), "=r"((R)[1]), "=r"((R)[2]), "=r"((R)[3]) : "r"(addr))
#define CP16(s, g) \
    asm volatile("cp.async.cg.shared.global [%0], [%1], 16;" :: "r"(s), "l"(g))
#define CP_COMMIT() asm volatile("cp.async.commit_group;" ::: "memory")
#define CP_WAIT(N)  asm volatile("cp.async.wait_group %0;" :: "n"(N) : "memory")

static __device__ __forceinline__ void mma16816h(float* c, const uint32_t* a,
                                                 const uint32_t* b) {
    asm volatile("mma.sync.aligned.m16n8k16.row.col.f32.f16.f16.f32 "
                 "{%0,%1,%2,%3},{%4,%5,%6,%7},{%8,%9},{%0,%1,%2,%3};"
                 : "+f"(c[0]), "+f"(c[1]), "+f"(c[2]), "+f"(c[3])
                 : "r"(a[0]), "r"(a[1]), "r"(a[2]), "r"(a[3]),
                   "r"(b[0]), "r"(b[1]));
}
static __device__ __forceinline__ uint32_t pkh(__half a, __half b) {
    return (uint32_t)__half_as_ushort(a) | ((uint32_t)__half_as_ushort(b) << 16);
}
static __device__ __forceinline__ uint32_t pkf(float a, float b) {
    return pkh(__float2half(a), __float2half(b));
}
static __device__ __forceinline__ uint32_t sq2(uint32_t u) {
    __half2 h = *reinterpret_cast<__half2*>(&u);
    h = __hmul2(h, h);
    return *reinterpret_cast<uint32_t*>(&h);
}

// ---------------- prep -------------------------------------------------------
__global__ __launch_bounds__(256) void prep_kernel(const float* __restrict__ Wmu0,
                                                   const float* __restrict__ Wlv0,
                                                   const float* __restrict__ Wmu1,
                                                   const float* __restrict__ Wlv1) {
    int id = blockIdx.x * 256 + threadIdx.x;
    if (id < R_DIM * D_IN) {
        int n = id >> 7, k = id & 127;
        float wm = Wmu0[(size_t)k * R_DIM + n];
        float wv = expf(Wlv0[(size_t)k * R_DIM + n]);
        g_w0m[id] = __float2half(wm);
        g_w0v[id] = __float2half(wv);
    }
    if (id < D_OUT * R_DIM) {
        int n = id >> 8, k = id & 255;
        float wm = Wmu1[(size_t)k * D_OUT + n];
        float e  = expf(Wlv1[(size_t)k * D_OUT + n]);
        g_w1m[id]  = __float2half(wm);
        g_w1a1[id] = __float2half(wm * wm + e);
        g_w1vh[id] = __float2half(e);
    }
    if (id < U_DIM * D_OUT) { g_sum_inv[id] = 0.f; g_sum_minv[id] = 0.f; }
}

// ============================================================================
// Fused kernel: 128 rows/block, 256 threads, 8 warps x 16 rows each.
// X A-fragments loaded ONCE into registers (Ax), x^2 fragments computed in
// registers (A2 = Ax*Ax); layer0 C-fragments repacked as layer1 A operands.
// W0 + W1 double-buffered, one commit group + one barrier per chunk.
//   L0 M = x*w0m,  L0 V = x2*w0v,
//   L1 M = m*w1m,  L1 V = v*a1 + m2*w1v.
// ============================================================================
__global__ __launch_bounds__(NTHR, 1) void fused_kernel(const float* __restrict__ X,
                                                        const int* __restrict__ X_idx) {
    extern __shared__ char sm[];
    const uint32_t sb = smem_u32(sm);
    const int t = threadIdx.x, lane = t & 31, wid = t >> 5;
    const int rowBase = blockIdx.x * BM;
    const int lr = lane & 7, sel = lane >> 3;

    // ---- prologue: prefetch W0[0] + W1[0] into stage 0, one group ------------
    #pragma unroll
    for (int it = 0; it < 2; it++) {
        int idx = t + it * NTHR;
        int r = idx >> 4, kk = idx & 15;
        uint32_t so = sb + S_W0 + r * P0B + kk * 16;
        size_t go = (size_t)r * D_IN + kk * 8;
        CP16(so,          (const char*)&g_w0m[go]);
        CP16(so + W0_MAT, (const char*)&g_w0v[go]);
    }
    {
        int row = t >> 2, k16 = t & 3;
        size_t go = (size_t)row * R_DIM + k16 * 8;
        uint32_t so = sb + S_W1 + row * P1B + k16 * 16;
        CP16(so,              (const char*)&g_w1m[go]);
        CP16(so + W1_MAT,     (const char*)&g_w1a1[go]);
        CP16(so + 2 * W1_MAT, (const char*)&g_w1vh[go]);
    }
    CP_COMMIT();

    if (t < BM) {
        int r = rowBase + t;
        *(int*)(sm + S_UID + t * 4) = (r < N_ROWS) ? X_idx[r] : -1;
    }

    // ---- phase 0: X tile 128 x 128 -> x (fp16) only ----------------------------
    #pragma unroll
    for (int it = 0; it < 16; it++) {
        int idx = t + it * NTHR;
        int row = idx >> 5;
        int k4  = (idx & 31) * 4;
        float4 v = make_float4(0.f, 0.f, 0.f, 0.f);
        if (rowBase + row < N_ROWS)
            v = *(const float4*)&X[(size_t)(rowBase + row) * D_IN + k4];
        int o = row * P0B + k4 * 2;
        *(uint32_t*)(sm + S_XH + o)     = pkf(v.x, v.y);
        *(uint32_t*)(sm + S_XH + o + 4) = pkf(v.z, v.w);
    }

    // persistent register state
    uint32_t Ax[8][4], A2[8][4];         // X / X^2 A-fragments (full K=128)
    float acc1M[8][4], acc1V[8][4];      // layer1 accumulators (16 rows x 64 cols)
    #pragma unroll
    for (int b = 0; b < 8; b++)
        #pragma unroll
        for (int c = 0; c < 4; c++) { acc1M[b][c] = 0.f; acc1V[b][c] = 0.f; }

    for (int nc = 0; nc < 8; nc++) {
        CP_WAIT(0);                      // W0[nc] + W1[nc] arrived
        __syncthreads();                 // visible to all; prev-chunk reads done

        if (nc == 0) {
            // ---- hoisted: load all X fragments once, square in registers ------
            #pragma unroll
            for (int ks = 0; ks < 8; ks++) {
                int ar = wid * 16 + lr + (sel & 1) * 8;
                int ac = ks * 16 + (sel >> 1) * 8;
                uint32_t off = (uint32_t)(ar * P0B + ac * 2);
                LDSM4(Ax[ks], sb + S_XH + off);
                #pragma unroll
                for (int e = 0; e < 4; e++) A2[ks][e] = sq2(Ax[ks][e]);
            }
        }

        // ---- issue W0[nc+1] + W1[nc+1] into stage (nc+1)&1, one group ----------
        if (nc < 7) {
            uint32_t b0 = sb + S_W0 + ((nc + 1) & 1) * W0_STAGE;
            #pragma unroll
            for (int it = 0; it < 2; it++) {
                int idx = t + it * NTHR;
                int r = idx >> 4, kk = idx & 15;
                size_t go = (size_t)((nc + 1) * 32 + r) * D_IN + kk * 8;
                uint32_t so = b0 + r * P0B + kk * 16;
                CP16(so,          (const char*)&g_w0m[go]);
                CP16(so + W0_MAT, (const char*)&g_w0v[go]);
            }
            uint32_t b1 = sb + S_W1 + ((nc + 1) & 1) * W1_STAGE;
            int row = t >> 2, k16 = t & 3;
            size_t go = (size_t)row * R_DIM + (nc + 1) * 32 + k16 * 8;
            uint32_t so = b1 + row * P1B + k16 * 16;
            CP16(so,              (const char*)&g_w1m[go]);
            CP16(so + W1_MAT,     (const char*)&g_w1a1[go]);
            CP16(so + 2 * W1_MAT, (const char*)&g_w1vh[go]);
        }
        CP_COMMIT();

        const uint32_t w0b = sb + S_W0 + (nc & 1) * W0_STAGE;
        const uint32_t w1b = sb + S_W1 + (nc & 1) * W1_STAGE;

        // ---- layer0: warp tile 16(m) x 32(n), K=128 (A in registers) -----------
        float a0M[4][4], a0V[4][4];
        #pragma unroll
        for (int b = 0; b < 4; b++)
            #pragma unroll
            for (int c = 0; c < 4; c++) { a0M[b][c] = 0.f; a0V[b][c] = 0.f; }

        #pragma unroll
        for (int ks = 0; ks < 8; ks++) {
            const int k = ks * 16;
            #pragma unroll
            for (int g = 0; g < 2; g++) {
                uint32_t Bm[4], Bv[4];
                int br = g * 16 + lr + (sel >> 1) * 8;
                int bc = k + (sel & 1) * 8;
                uint32_t off = (uint32_t)(br * P0B + bc * 2);
                LDSM4(Bm, w0b + off);
                LDSM4(Bv, w0b + W0_MAT + off);
                #pragma unroll
                for (int q = 0; q < 2; q++) {
                    int n8 = g * 2 + q;
                    mma16816h(a0M[n8], Ax[ks], &Bm[q * 2]);
                    mma16816h(a0V[n8], A2[ks], &Bv[q * 2]);
                }
            }
        }

        // ---- gate + square + pack C-fragments into layer1 A-fragments ----------
        uint32_t Am[2][4], Av[2][4], A2m[2][4];   // [ko(k16)][a0..a3]
        #pragma unroll
        for (int n8 = 0; n8 < 4; n8++) {
            float gm[4], gv[4];
            #pragma unroll
            for (int e = 0; e < 4; e++) {
                float m = a0M[n8][e];
                bool g = m > 0.f;
                gm[e] = g ? m : 0.f;
                gv[e] = g ? a0V[n8][e] : 0.f;
            }
            int ko = n8 >> 1, hi = (n8 & 1) * 2;
            Am[ko][hi]      = pkf(gm[0], gm[1]);
            Am[ko][hi + 1]  = pkf(gm[2], gm[3]);
            Av[ko][hi]      = pkf(gv[0], gv[1]);
            Av[ko][hi + 1]  = pkf(gv[2], gv[3]);
            A2m[ko][hi]     = pkf(gm[0] * gm[0], gm[1] * gm[1]);
            A2m[ko][hi + 1] = pkf(gm[2] * gm[2], gm[3] * gm[3]);
        }

        // ---- layer1: warp tile 16(m) x 64(n), K=32 (A in registers) ------------
        #pragma unroll
        for (int ko = 0; ko < 2; ko++) {
            #pragma unroll
            for (int g = 0; g < 4; g++) {
                uint32_t Bm[4], Ba[4], Bv[4];
                int br = g * 16 + lr + (sel >> 1) * 8;
                int bc = ko * 16 + (sel & 1) * 8;
                uint32_t off = (uint32_t)(br * P1B + bc * 2);
                LDSM4(Bm, w1b + off);
                LDSM4(Ba, w1b + W1_MAT + off);
                LDSM4(Bv, w1b + 2 * W1_MAT + off);
                #pragma unroll
                for (int q = 0; q < 2; q++) {
                    int n8 = g * 2 + q;
                    mma16816h(acc1M[n8], Am[ko], &Bm[q * 2]);
                    mma16816h(acc1V[n8], Av[ko], &Ba[q * 2]);
                    mma16816h(acc1V[n8], A2m[ko], &Bv[q * 2]);
                }
            }
        }
    }

    __syncthreads();                     // all smem reads done before overlay

    // ---- epilogue: inv-variance weighting into smem staging --------------------
    float* sInv  = (float*)(sm + S_SINV);
    float* sMinv = (float*)(sm + S_SMINV);
    #pragma unroll
    for (int n8 = 0; n8 < 8; n8++) {
        int col = n8 * 8 + 2 * (lane & 3);
        #pragma unroll
        for (int half = 0; half < 2; half++) {
            int lrow = wid * 16 + (lane >> 2) + half * 8;
            float m0 = acc1M[n8][half * 2 + 0];
            float m1 = acc1M[n8][half * 2 + 1];
            float V0 = fmaxf(acc1V[n8][half * 2 + 0], EPS);
            float V1 = fmaxf(acc1V[n8][half * 2 + 1], EPS);
            float i0 = 1.f / V0, i1 = 1.f / V1;
            sInv[lrow * 65 + col]      = i0;
            sInv[lrow * 65 + col + 1]  = i1;
            sMinv[lrow * 65 + col]     = m0 * i0;
            sMinv[lrow * 65 + col + 1] = m1 * i1;
        }
    }
    __syncthreads();

    // ---- block-level segmented reduce over sorted uids -> atomics ---------------
    const int* uids = (const int*)(sm + S_UID);
    int col = t & 63, grp = t >> 6;            // 4 groups x 32 rows
    float aI = 0.f, aM = 0.f;
    int cur = -1;
    for (int r0 = 0; r0 < 32; r0++) {
        int row = grp * 32 + r0;
        int uid = uids[row];
        if (uid != cur) {
            if (cur >= 0) {
                atomicAdd(&g_sum_inv[cur * D_OUT + col], aI);
                atomicAdd(&g_sum_minv[cur * D_OUT + col], aM);
            }
            cur = uid; aI = 0.f; aM = 0.f;
        }
        if (uid >= 0) {
            aI += sInv[row * 65 + col];
            aM += sMinv[row * 65 + col];
        }
    }
    if (cur >= 0) {
        atomicAdd(&g_sum_inv[cur * D_OUT + col], aI);
        atomicAdd(&g_sum_minv[cur * D_OUT + col], aM);
    }
}

// ---------------- finalize ----------------------------------------------------
__global__ __launch_bounds__(256) void finalize_kernel(float* __restrict__ out) {
    int id = blockIdx.x * 256 + threadIdx.x;
    if (id < U_DIM * D_OUT) {
        float var = 1.f / (g_sum_inv[id] + EPS);
        out[id]                 = g_sum_minv[id] * var;
        out[U_DIM * D_OUT + id] = var;
    }
}

// ---------------- launch -------------------------------------------------------
extern "C" void kernel_launch(void* const* d_in, const int* in_sizes, int n_in,
                              void* d_out, int out_size) {
    const float* X     = (const float*)d_in[0];
    const int*   X_idx = (const int*)d_in[1];
    const float* Wmu0  = (const float*)d_in[2];
    const float* Wlv0  = (const float*)d_in[3];
    const float* Wmu1  = (const float*)d_in[4];
    const float* Wlv1  = (const float*)d_in[5];
    float* out = (float*)d_out;
    (void)in_sizes; (void)n_in; (void)out_size;

    cudaFuncSetAttribute(fused_kernel, cudaFuncAttributeMaxDynamicSharedMemorySize,
                         SMEM_SZ);

    const int nBlocks = (N_ROWS + BM - 1) / BM;

    prep_kernel<<<(U_DIM * D_OUT + 255) / 256, 256>>>(Wmu0, Wlv0, Wmu1, Wlv1);
    fused_kernel<<<nBlocks, NTHR, SMEM_SZ>>>(X, X_idx);
    finalize_kernel<<<(U_DIM * D_OUT + 255) / 256, 256>>>(out);
}